// round 3
// baseline (speedup 1.0000x reference)
#include <cuda_runtime.h>
#include <cstdint>

#define NPTS 262144
#define CHN 96
#define KOFF 27
#define TM 128
#define KK 32
#define NTHREADS 256
#define NTILES 81   // KOFF * CHN / KK

// Intermediate activations between the two conv layers (100 MB, static — no allocs).
__device__ float g_x1[(size_t)NPTS * CHN];

// One gather-GEMM-scatter sparse-conv layer:
//   out[p][c] = PReLU( sum_k sum_j (mask[k][p] ? fin[idx[k][p]][j] : 0) * W[k][j][c]
//               + bias[c] + (resid ? resid[p][c] : 0), alpha )
__global__ void __launch_bounds__(NTHREADS, 2)
sconv_kernel(const float* __restrict__ fin,
             const float* __restrict__ resid,      // nullptr for layer 1
             const int* __restrict__ nidx,         // [K, N]
             const int* __restrict__ nmask,        // [K, N] (bool stored as int32)
             const float* __restrict__ W,          // [K, CH, CH]
             const float* __restrict__ bias,       // [CH]
             const float* __restrict__ alpha,      // [1]
             float* __restrict__ out)              // [N, CH]
{
    __shared__ float As[KK][TM + 4];     // gathered features, [kk][pt], 16B-aligned rows
    __shared__ float Bs[KK][CHN];        // weight tile [kk][c]
    __shared__ int   sIdxM[KOFF][TM];    // idx with mask folded in (-1 = masked out)

    const int tid  = threadIdx.x;
    const int base = blockIdx.x * TM;

    // Preload neighbor indices for this block's points; fold mask into sign.
    for (int o = tid; o < KOFF * TM; o += NTHREADS) {
        const int k = o / TM, t = o % TM;
        const int row = nidx[(size_t)k * NPTS + base + t];
        const int m   = nmask[(size_t)k * NPTS + base + t];
        sIdxM[k][t] = m ? row : -1;
    }

    // Compute-thread mapping: 8 channel-columns x 32 point-rows.
    const int tx = tid & 7;          // c0 = tx*12  (6 f32x2 pairs)
    const int ty = tid >> 3;         // t0 = ty*4   (4 points)
    const int c0 = tx * 12;
    const int t0 = ty * 4;

    // Gather-fill mapping: 2 threads per point, 16 consecutive floats each.
    const int gpt = tid & 127;       // point 0..127
    const int gh  = tid >> 7;        // half of the 32-wide j-slice

    unsigned long long acc[4][6];    // 4 points x 6 channel-pairs (f32x2)
    #pragma unroll
    for (int t = 0; t < 4; ++t)
        #pragma unroll
        for (int p = 0; p < 6; ++p) acc[t][p] = 0ull;

    __syncthreads();

    for (int tile = 0; tile < NTILES; ++tile) {
        const int k  = tile / 3;
        const int j0 = (tile % 3) * KK;

        // ---- fill As: masked gather, transposed into [kk][pt] ----
        {
            const int row = sIdxM[k][gpt];
            float vv[16];
            float4* vv4 = reinterpret_cast<float4*>(vv);
            if (row >= 0) {
                const float4* src = reinterpret_cast<const float4*>(
                    fin + (size_t)row * CHN + j0 + gh * 16);
                vv4[0] = src[0]; vv4[1] = src[1]; vv4[2] = src[2]; vv4[3] = src[3];
            } else {
                const float4 z = make_float4(0.f, 0.f, 0.f, 0.f);
                vv4[0] = z; vv4[1] = z; vv4[2] = z; vv4[3] = z;
            }
            const int jb = gh * 16;
            #pragma unroll
            for (int i = 0; i < 16; ++i) As[jb + i][gpt] = vv[i];
        }

        // ---- fill Bs: W[k][j0..j0+31][0..95] (contiguous 3072 floats) ----
        {
            const float* wsrc = W + (size_t)k * CHN * CHN + (size_t)j0 * CHN;
            float* bdst = &Bs[0][0];
            #pragma unroll
            for (int pass = 0; pass < 3; ++pass) {
                const int o = (tid + pass * NTHREADS) * 4;
                *reinterpret_cast<float4*>(bdst + o) =
                    *reinterpret_cast<const float4*>(wsrc + o);
            }
        }
        __syncthreads();

        // ---- compute: 32 reduction steps, 24 packed FMAs each ----
        #pragma unroll
        for (int kk = 0; kk < KK; ++kk) {
            const float4 av = *reinterpret_cast<const float4*>(&As[kk][t0]);
            unsigned long long gp[4];
            asm("mov.b64 %0, {%1, %1};" : "=l"(gp[0]) : "f"(av.x));
            asm("mov.b64 %0, {%1, %1};" : "=l"(gp[1]) : "f"(av.y));
            asm("mov.b64 %0, {%1, %1};" : "=l"(gp[2]) : "f"(av.z));
            asm("mov.b64 %0, {%1, %1};" : "=l"(gp[3]) : "f"(av.w));

            const unsigned long long* brow =
                reinterpret_cast<const unsigned long long*>(&Bs[kk][c0]);
            #pragma unroll
            for (int p = 0; p < 6; ++p) {
                const unsigned long long wp = brow[p];
                #pragma unroll
                for (int t = 0; t < 4; ++t)
                    asm("fma.rn.f32x2 %0, %1, %2, %0;"
                        : "+l"(acc[t][p]) : "l"(gp[t]), "l"(wp));
            }
        }
        __syncthreads();
    }

    // ---- epilogue: bias, optional residual, PReLU, store ----
    const float a0 = alpha[0];
    float bi[12];
    {
        float4* b4 = reinterpret_cast<float4*>(bi);
        const float4* bsrc = reinterpret_cast<const float4*>(bias + c0);
        b4[0] = bsrc[0]; b4[1] = bsrc[1]; b4[2] = bsrc[2];
    }
    #pragma unroll
    for (int t = 0; t < 4; ++t) {
        const size_t pt = (size_t)(base + t0 + t);
        float v[12];
        #pragma unroll
        for (int p = 0; p < 6; ++p) {
            float x0, x1;
            asm("mov.b64 {%0, %1}, %2;" : "=f"(x0), "=f"(x1) : "l"(acc[t][p]));
            v[2 * p]     = x0 + bi[2 * p];
            v[2 * p + 1] = x1 + bi[2 * p + 1];
        }
        if (resid != nullptr) {
            const float4* r4 = reinterpret_cast<const float4*>(resid + pt * CHN + c0);
            float rr[12];
            float4* rr4 = reinterpret_cast<float4*>(rr);
            rr4[0] = r4[0]; rr4[1] = r4[1]; rr4[2] = r4[2];
            #pragma unroll
            for (int i = 0; i < 12; ++i) v[i] += rr[i];
        }
        #pragma unroll
        for (int i = 0; i < 12; ++i) v[i] = (v[i] > 0.f) ? v[i] : a0 * v[i];
        float4* o4 = reinterpret_cast<float4*>(out + pt * CHN + c0);
        const float4* v4 = reinterpret_cast<const float4*>(v);
        o4[0] = v4[0]; o4[1] = v4[1]; o4[2] = v4[2];
    }
}

extern "C" void kernel_launch(void* const* d_in, const int* in_sizes, int n_in,
                              void* d_out, int out_size)
{
    const float* feats = (const float*)d_in[0];
    const int*   idx   = (const int*)d_in[1];
    const int*   mask  = (const int*)d_in[2];
    const float* W1    = (const float*)d_in[3];
    const float* b1    = (const float*)d_in[4];
    const float* a1    = (const float*)d_in[5];
    const float* W2    = (const float*)d_in[6];
    const float* b2    = (const float*)d_in[7];
    const float* a2    = (const float*)d_in[8];
    float*       out   = (float*)d_out;

    float* x1 = nullptr;
    cudaGetSymbolAddress((void**)&x1, g_x1);

    dim3 grid(NPTS / TM), block(NTHREADS);
    sconv_kernel<<<grid, block>>>(feats, nullptr, idx, mask, W1, b1, a1, x1);
    sconv_kernel<<<grid, block>>>(x1,    feats,   idx, mask, W2, b2, a2, out);
}

// round 6
// speedup vs baseline: 1.5903x; 1.5903x over previous
#include <cuda_runtime.h>
#include <cuda_bf16.h>
#include <cstdint>

#define NPTS 262144
#define CHN 96
#define KOFF 27
#define NCHUNK 81           // 27 offsets x 3 chunks of 32 fp32-K each
#define NTHREADS 256

// SMEM layout (dynamic):
#define SIDX_OFF 0          // int[27][128] = 13824 B
#define A_OFF    13824      // 2 bufs x (hi 10240 + lo 10240) = 40960 B  (stride 80B/row)
#define W_OFF    54784      // 2 bufs x (hi 6656 + lo 6656)   = 26624 B  (stride 208B/row)
#define SMEMTOT  81408

// ---------------- static device buffers (no allocs allowed) ----------------
__device__ __align__(16) uint32_t g_fsplit[(size_t)NPTS * CHN];   // feats (hi,lo) packed
__device__ __align__(16) uint32_t g_x1split[(size_t)NPTS * CHN];  // layer-1 out, packed
// W pre-split, padded: [2 layers][81 chunks][32 k][104 n] bf16
__device__ __align__(16) __nv_bfloat16 g_Whi[2 * NCHUNK * 32 * 104];
__device__ __align__(16) __nv_bfloat16 g_Wlo[2 * NCHUNK * 32 * 104];

// ---------------- helpers ----------------
__device__ __forceinline__ uint32_t smem_u32(const void* p) {
    uint32_t a;
    asm("{ .reg .u64 t; cvta.to.shared.u64 t, %1; cvt.u32.u64 %0, t; }" : "=r"(a) : "l"(p));
    return a;
}
__device__ __forceinline__ uint32_t prmt(uint32_t a, uint32_t b, uint32_t s) {
    uint32_t d;
    asm("prmt.b32 %0, %1, %2, %3;" : "=r"(d) : "r"(a), "r"(b), "r"(s));
    return d;
}
__device__ __forceinline__ void ldm4(uint32_t* r, uint32_t addr) {
    asm volatile("ldmatrix.sync.aligned.m8n8.x4.shared.b16 {%0,%1,%2,%3}, [%4];"
        : "=r"(r[0]), "=r"(r[1]), "=r"(r[2]), "=r"(r[3]) : "r"(addr));
}
__device__ __forceinline__ void ldm4t(uint32_t* r, uint32_t addr) {
    asm volatile("ldmatrix.sync.aligned.m8n8.x4.trans.shared.b16 {%0,%1,%2,%3}, [%4];"
        : "=r"(r[0]), "=r"(r[1]), "=r"(r[2]), "=r"(r[3]) : "r"(addr));
}
__device__ __forceinline__ void mma16816(float* d, const uint32_t* a, uint32_t b0, uint32_t b1) {
    asm volatile("mma.sync.aligned.m16n8k16.row.col.f32.bf16.bf16.f32 "
        "{%0,%1,%2,%3},{%4,%5,%6,%7},{%8,%9},{%0,%1,%2,%3};"
        : "+f"(d[0]), "+f"(d[1]), "+f"(d[2]), "+f"(d[3])
        : "r"(a[0]), "r"(a[1]), "r"(a[2]), "r"(a[3]), "r"(b0), "r"(b1));
}
__device__ __forceinline__ uint32_t pack_split(float x) {
    __nv_bfloat16 hi = __float2bfloat16(x);
    __nv_bfloat16 lo = __float2bfloat16(x - __bfloat162float(hi));
    return (uint32_t)__bfloat16_as_ushort(hi) | ((uint32_t)__bfloat16_as_ushort(lo) << 16);
}

// ---------------- prep kernels ----------------
__global__ void split_kernel(const float* __restrict__ src, uint32_t* __restrict__ dst, int n) {
    int i = blockIdx.x * blockDim.x + threadIdx.x;
    if (i < n) dst[i] = pack_split(src[i]);
}

__global__ void wprep_kernel(const float* __restrict__ W1, const float* __restrict__ W2) {
    int i = blockIdx.x * blockDim.x + threadIdx.x;      // over 2*81*32*104
    if (i >= 2 * NCHUNK * 32 * 104) return;
    int n = i % 104;
    int rest = i / 104;
    int kk = rest % 32;
    int c  = (rest / 32) % NCHUNK;
    int layer = rest / (32 * NCHUNK);
    float w = 0.f;
    if (n < CHN) {
        int k = c / 3, j = (c % 3) * 32 + kk;
        const float* W = layer ? W2 : W1;
        w = W[(size_t)k * CHN * CHN + (size_t)j * CHN + n];
    }
    __nv_bfloat16 hi = __float2bfloat16(w);
    __nv_bfloat16 lo = __float2bfloat16(w - __bfloat162float(hi));
    g_Whi[i] = hi;
    g_Wlo[i] = lo;
}

// ---------------- main gather-GEMM layer kernel (HMMA) ----------------
__global__ void __launch_bounds__(NTHREADS, 2)
sconv_hmma(const uint32_t* __restrict__ fin,   // split input [N, CH] packed
           const float* __restrict__ resid,    // fp32 residual or nullptr
           const int* __restrict__ nidx, const int* __restrict__ nmask,
           const __nv_bfloat16* __restrict__ Whi,   // [81][32][104], layer slice
           const __nv_bfloat16* __restrict__ Wlo,
           const float* __restrict__ bias, const float* __restrict__ alpha,
           void* __restrict__ outp, int out_split)
{
    extern __shared__ unsigned char smem[];
    const uint32_t sbase = smem_u32(smem);
    const int tid = threadIdx.x;
    const int wid = tid >> 5, l = tid & 31;
    const int base = blockIdx.x * 128;
    int* sIdx = (int*)(smem + SIDX_OFF);

    // preload idx with mask folded in
    for (int o = tid; o < KOFF * 128; o += NTHREADS) {
        const int k = o >> 7, t = o & 127;
        const int row = nidx[(size_t)k * NPTS + base + t];
        sIdx[o] = nmask[(size_t)k * NPTS + base + t] ? row : -1;
    }
    __syncthreads();

    const int mrow = (wid & 3) * 32;     // warp M offset (32 pts)
    const int ncol = (wid >> 2) * 48;    // warp N offset (48 ch)

    float acc[2][6][4];
    #pragma unroll
    for (int mt = 0; mt < 2; ++mt)
        #pragma unroll
        for (int nt = 0; nt < 6; ++nt)
            #pragma unroll
            for (int q = 0; q < 4; ++q) acc[mt][nt][q] = 0.f;

    const int grow = tid >> 1, ghalf = tid & 1;   // gather: 2 thr/point, 16 words each

    auto fill = [&](int c, int buf) {
        const int k = c / 3, cpart = c % 3;
        // ---- A gather + split unpack ----
        const int gidx = sIdx[(k << 7) + grow];
        uint4 v[4];
        if (gidx >= 0) {
            const uint4* src = (const uint4*)(fin + (size_t)gidx * CHN + cpart * 32 + ghalf * 16);
            v[0] = src[0]; v[1] = src[1]; v[2] = src[2]; v[3] = src[3];
        } else {
            v[0] = v[1] = v[2] = v[3] = make_uint4(0u, 0u, 0u, 0u);
        }
        unsigned char* aH = smem + A_OFF + buf * 20480;
        unsigned char* aL = aH + 10240;
        #pragma unroll
        for (int i = 0; i < 4; ++i) {
            uint32_t h0 = prmt(v[i].x, v[i].y, 0x5410u);
            uint32_t h1 = prmt(v[i].z, v[i].w, 0x5410u);
            uint32_t l0 = prmt(v[i].x, v[i].y, 0x7632u);
            uint32_t l1 = prmt(v[i].z, v[i].w, 0x7632u);
            const int bo = grow * 80 + (ghalf * 16 + i * 4) * 2;
            *(uint2*)(aH + bo) = make_uint2(h0, h1);
            *(uint2*)(aL + bo) = make_uint2(l0, l1);
        }
        // ---- W copy (pre-split, pre-padded, contiguous 6656B per matrix) ----
        const uint4* sH = (const uint4*)(Whi + (size_t)c * 3328);
        const uint4* sL = (const uint4*)(Wlo + (size_t)c * 3328);
        uint4* dH = (uint4*)(smem + W_OFF + buf * 13312);
        uint4* dL = (uint4*)(smem + W_OFF + buf * 13312 + 6656);
        #pragma unroll
        for (int j = tid; j < 416; j += NTHREADS) {
            dH[j] = sH[j];
            dL[j] = sL[j];
        }
    };

    fill(0, 0);
    __syncthreads();

    // ldmatrix lane addressing pieces
    const int arow_off = (l & 7) + ((l >> 3) & 1) * 8;   // row within 16
    const int acol_off = ((l >> 4) & 1) * 8;             // k-col half

    for (int c = 0; c < NCHUNK; ++c) {
        const int buf = c & 1;
        if (c + 1 < NCHUNK) fill(c + 1, (c + 1) & 1);

        const uint32_t aBH = sbase + A_OFF + buf * 20480;
        const uint32_t aBL = aBH + 10240;
        const uint32_t wBH = sbase + W_OFF + buf * 13312;
        const uint32_t wBL = wBH + 6656;

        #pragma unroll
        for (int kh = 0; kh < 2; ++kh) {
            uint32_t ah[2][4], al[2][4];
            #pragma unroll
            for (int mt = 0; mt < 2; ++mt) {
                const int r = mrow + mt * 16 + arow_off;
                const uint32_t off = (uint32_t)(r * 80 + (kh * 16 + acol_off) * 2);
                ldm4(ah[mt], aBH + off);
                ldm4(al[mt], aBL + off);
            }
            const int kr = kh * 16 + arow_off;
            #pragma unroll
            for (int np = 0; np < 3; ++np) {
                const int nc = ncol + np * 16 + acol_off;
                const uint32_t woff = (uint32_t)(kr * 208 + nc * 2);
                uint32_t bh[4], bl[4];
                ldm4t(bh, wBH + woff);
                ldm4t(bl, wBL + woff);
                #pragma unroll
                for (int hf = 0; hf < 2; ++hf) {
                    const int nt = np * 2 + hf;
                    #pragma unroll
                    for (int mt = 0; mt < 2; ++mt) {
                        mma16816(acc[mt][nt], ah[mt], bh[2 * hf], bh[2 * hf + 1]); // hi*hi
                        mma16816(acc[mt][nt], ah[mt], bl[2 * hf], bl[2 * hf + 1]); // hi*lo
                        mma16816(acc[mt][nt], al[mt], bh[2 * hf], bh[2 * hf + 1]); // lo*hi
                    }
                }
            }
        }
        __syncthreads();
    }

    // ---- epilogue: bias, optional residual, PReLU, store from mma accum regs ----
    const float a0 = alpha[0];
    float2 b2[6];
    #pragma unroll
    for (int nt = 0; nt < 6; ++nt) {
        const int col = ncol + nt * 8 + (l & 3) * 2;
        b2[nt] = make_float2(bias[col], bias[col + 1]);
    }
    #pragma unroll
    for (int mt = 0; mt < 2; ++mt) {
        #pragma unroll
        for (int half = 0; half < 2; ++half) {
            const size_t pt = (size_t)(base + mrow + mt * 16 + (l >> 2) + half * 8);
            #pragma unroll
            for (int nt = 0; nt < 6; ++nt) {
                const int col = ncol + nt * 8 + (l & 3) * 2;
                float v0 = acc[mt][nt][2 * half]     + b2[nt].x;
                float v1 = acc[mt][nt][2 * half + 1] + b2[nt].y;
                if (resid != nullptr) {
                    const float2 r = *(const float2*)(resid + pt * CHN + col);
                    v0 += r.x; v1 += r.y;
                }
                v0 = (v0 > 0.f) ? v0 : a0 * v0;
                v1 = (v1 > 0.f) ? v1 : a0 * v1;
                if (out_split) {
                    *(uint2*)((uint32_t*)outp + pt * CHN + col) =
                        make_uint2(pack_split(v0), pack_split(v1));
                } else {
                    *(float2*)((float*)outp + pt * CHN + col) = make_float2(v0, v1);
                }
            }
        }
    }
}

extern "C" void kernel_launch(void* const* d_in, const int* in_sizes, int n_in,
                              void* d_out, int out_size)
{
    const float* feats = (const float*)d_in[0];
    const int*   idx   = (const int*)d_in[1];
    const int*   mask  = (const int*)d_in[2];
    const float* W1    = (const float*)d_in[3];
    const float* b1    = (const float*)d_in[4];
    const float* a1    = (const float*)d_in[5];
    const float* W2    = (const float*)d_in[6];
    const float* b2    = (const float*)d_in[7];
    const float* a2    = (const float*)d_in[8];

    uint32_t *fsplit, *x1split;
    __nv_bfloat16 *whi, *wlo;
    cudaGetSymbolAddress((void**)&fsplit, g_fsplit);
    cudaGetSymbolAddress((void**)&x1split, g_x1split);
    cudaGetSymbolAddress((void**)&whi, g_Whi);
    cudaGetSymbolAddress((void**)&wlo, g_Wlo);

    static bool attr_done = false;
    if (!attr_done) {
        cudaFuncSetAttribute(sconv_hmma, cudaFuncAttributeMaxDynamicSharedMemorySize, SMEMTOT);
        attr_done = true;
    }

    const int nelem = NPTS * CHN;
    split_kernel<<<(nelem + 255) / 256, 256>>>(feats, fsplit, nelem);
    const int nw = 2 * NCHUNK * 32 * 104;
    wprep_kernel<<<(nw + 255) / 256, 256>>>(W1, W2);

    const size_t wstride = (size_t)NCHUNK * 32 * 104;
    dim3 grid(NPTS / 128), block(NTHREADS);
    sconv_hmma<<<grid, block, SMEMTOT>>>(fsplit, nullptr, idx, mask,
                                         whi, wlo, b1, a1, (void*)x1split, 1);
    sconv_hmma<<<grid, block, SMEMTOT>>>(x1split, feats, idx, mask,
                                         whi + wstride, wlo + wstride,
                                         b2, a2, d_out, 0);
}

// round 7
// speedup vs baseline: 4.1657x; 2.6195x over previous
#include <cuda_runtime.h>
#include <cuda_fp16.h>
#include <cstdint>

#define NPTS 262144
#define CHN 96
#define KOFF 27
#define NCHUNK 81           // 27 offsets x 3 chunks of 32 K each
#define NTHREADS 256

// SMEM layout (dynamic):
#define SIDX_OFF 0          // int[27][128] = 13824 B
#define A_OFF    13824      // 2 bufs x 10240 B (128 rows x 80B stride, fp16)
#define W_OFF    34304      // 2 bufs x 13312 B (hi 6656 + lo 6656)
#define SMEMTOT  60928

// ---------------- static device buffers (no allocs allowed) ----------------
__device__ __align__(16) __half g_fh[(size_t)NPTS * CHN];    // feats fp16
__device__ __align__(16) __half g_x1h[(size_t)NPTS * CHN];   // layer-1 out fp16
// W split: [2 layers][81 chunks][2 (hi,lo)][32 k][104 n] fp16; chunk = 6656 halfs
__device__ __align__(16) __half g_Wsp[2 * NCHUNK * 2 * 32 * 104];

// ---------------- helpers ----------------
__device__ __forceinline__ uint32_t smem_u32(const void* p) {
    uint32_t a;
    asm("{ .reg .u64 t; cvta.to.shared.u64 t, %1; cvt.u32.u64 %0, t; }" : "=r"(a) : "l"(p));
    return a;
}
__device__ __forceinline__ void cpa16(uint32_t d, const void* s, int sz) {
    asm volatile("cp.async.cg.shared.global [%0], [%1], 16, %2;"
        :: "r"(d), "l"(__cvta_generic_to_global(s)), "r"(sz) : "memory");
}
__device__ __forceinline__ void ldm4(uint32_t* r, uint32_t addr) {
    asm volatile("ldmatrix.sync.aligned.m8n8.x4.shared.b16 {%0,%1,%2,%3}, [%4];"
        : "=r"(r[0]), "=r"(r[1]), "=r"(r[2]), "=r"(r[3]) : "r"(addr));
}
__device__ __forceinline__ void ldm4t(uint32_t* r, uint32_t addr) {
    asm volatile("ldmatrix.sync.aligned.m8n8.x4.trans.shared.b16 {%0,%1,%2,%3}, [%4];"
        : "=r"(r[0]), "=r"(r[1]), "=r"(r[2]), "=r"(r[3]) : "r"(addr));
}
__device__ __forceinline__ void mma16816(float* d, const uint32_t* a, uint32_t b0, uint32_t b1) {
    asm volatile("mma.sync.aligned.m16n8k16.row.col.f32.f16.f16.f32 "
        "{%0,%1,%2,%3},{%4,%5,%6,%7},{%8,%9},{%0,%1,%2,%3};"
        : "+f"(d[0]), "+f"(d[1]), "+f"(d[2]), "+f"(d[3])
        : "r"(a[0]), "r"(a[1]), "r"(a[2]), "r"(a[3]), "r"(b0), "r"(b1));
}

// ---------------- prep kernels ----------------
__global__ void split_kernel(const float* __restrict__ src, __half* __restrict__ dst, int n) {
    int i = blockIdx.x * blockDim.x + threadIdx.x;
    if (i < n) dst[i] = __float2half(src[i]);
}

__global__ void wprep_kernel(const float* __restrict__ W1, const float* __restrict__ W2) {
    int i = blockIdx.x * blockDim.x + threadIdx.x;   // over 2*81*2*32*104
    if (i >= 2 * NCHUNK * 2 * 32 * 104) return;
    int n = i % 104;
    int rest = i / 104;
    int kk = rest % 32;  rest /= 32;
    int part = rest % 2; rest /= 2;
    int c = rest % NCHUNK;
    int layer = rest / NCHUNK;
    float w = 0.f;
    if (n < CHN) {
        int k = c / 3, j = (c % 3) * 32 + kk;
        const float* W = layer ? W2 : W1;
        w = W[(size_t)k * CHN * CHN + (size_t)j * CHN + n];
    }
    __half hi = __float2half(w);
    __half lo = __float2half(w - __half2float(hi));
    g_Wsp[i] = part ? lo : hi;
}

// ---------------- main gather-GEMM layer kernel (fp16 2-term HMMA) ----------------
__global__ void __launch_bounds__(NTHREADS, 2)
sconv_hmma(const __half* __restrict__ fin,    // fp16 input [N, CH]
           const float* __restrict__ resid,   // fp32 residual or nullptr
           const int* __restrict__ nidx, const int* __restrict__ nmask,
           const __half* __restrict__ Wsp,    // layer slice: [81][2][32][104]
           const float* __restrict__ bias, const float* __restrict__ alpha,
           void* __restrict__ outp, int out_half)
{
    extern __shared__ unsigned char smem[];
    const uint32_t sbase = smem_u32(smem);
    const int tid = threadIdx.x;
    const int wid = tid >> 5, l = tid & 31;
    const int base = blockIdx.x * 128;
    int* sIdx = (int*)(smem + SIDX_OFF);

    // preload idx with mask folded in
    for (int o = tid; o < KOFF * 128; o += NTHREADS) {
        const int k = o >> 7, t = o & 127;
        const int row = nidx[(size_t)k * NPTS + base + t];
        sIdx[o] = nmask[(size_t)k * NPTS + base + t] ? row : -1;
    }
    __syncthreads();

    const int mrow = (wid & 3) * 32;     // warp M offset (32 pts)
    const int ncol = (wid >> 2) * 48;    // warp N offset (48 ch)
    const int grow = tid >> 1, gh = tid & 1;   // gather: 2 thr/point, 16 halfs each

    float acc[2][6][4];
    #pragma unroll
    for (int mt = 0; mt < 2; ++mt)
        #pragma unroll
        for (int nt = 0; nt < 6; ++nt)
            #pragma unroll
            for (int q = 0; q < 4; ++q) acc[mt][nt][q] = 0.f;

    // async prefetch of chunk c into buffer buf
    auto prefetch = [&](int c, int buf) {
        const int k = c / 3, cpart = c % 3;
        // A gather (128 pts x 32 halfs, zero-fill masked rows)
        const int gidx = sIdx[(k << 7) + grow];
        const __half* gsrc = fin + (size_t)(gidx < 0 ? 0 : gidx) * CHN + cpart * 32 + gh * 16;
        const int sz = (gidx < 0) ? 0 : 16;
        const uint32_t sa = sbase + A_OFF + buf * 10240 + grow * 80 + gh * 32;
        cpa16(sa, gsrc, sz);
        cpa16(sa + 16, gsrc + 8, sz);
        // W copy: 13312 B contiguous = 832 uint4
        const uint4* ws = (const uint4*)(Wsp + (size_t)c * 6656);
        const uint32_t wd = sbase + W_OFF + buf * 13312;
        cpa16(wd + tid * 16,         ws + tid,       16);
        cpa16(wd + (tid + 256) * 16, ws + tid + 256, 16);
        cpa16(wd + (tid + 512) * 16, ws + tid + 512, 16);
        if (tid < 64) cpa16(wd + (tid + 768) * 16, ws + tid + 768, 16);
        asm volatile("cp.async.commit_group;" ::: "memory");
    };

    prefetch(0, 0);
    asm volatile("cp.async.wait_group 0;" ::: "memory");
    __syncthreads();

    // ldmatrix lane addressing
    const int arow_off = (l & 7) + ((l >> 3) & 1) * 8;
    const int acol_off = ((l >> 4) & 1) * 8;

    for (int c = 0; c < NCHUNK; ++c) {
        const int buf = c & 1;
        if (c + 1 < NCHUNK) prefetch(c + 1, (c + 1) & 1);

        const uint32_t aB  = sbase + A_OFF + buf * 10240;
        const uint32_t wBH = sbase + W_OFF + buf * 13312;
        const uint32_t wBL = wBH + 6656;

        #pragma unroll
        for (int kh = 0; kh < 2; ++kh) {
            uint32_t a[2][4];
            #pragma unroll
            for (int mt = 0; mt < 2; ++mt) {
                const int r = mrow + mt * 16 + arow_off;
                ldm4(a[mt], aB + (uint32_t)(r * 80 + (kh * 16 + acol_off) * 2));
            }
            const int kr = kh * 16 + arow_off;
            #pragma unroll
            for (int np = 0; np < 3; ++np) {
                const int nc = ncol + np * 16 + acol_off;
                const uint32_t woff = (uint32_t)(kr * 208 + nc * 2);
                uint32_t bh[4], bl[4];
                ldm4t(bh, wBH + woff);
                ldm4t(bl, wBL + woff);
                #pragma unroll
                for (int hf = 0; hf < 2; ++hf) {
                    const int nt = np * 2 + hf;
                    #pragma unroll
                    for (int mt = 0; mt < 2; ++mt) {
                        mma16816(acc[mt][nt], a[mt], bh[2 * hf], bh[2 * hf + 1]); // A*Whi
                        mma16816(acc[mt][nt], a[mt], bl[2 * hf], bl[2 * hf + 1]); // A*Wlo
                    }
                }
            }
        }
        if (c + 1 < NCHUNK)
            asm volatile("cp.async.wait_group 0;" ::: "memory");
        __syncthreads();
    }

    // ---- epilogue: bias, optional residual, PReLU, store from mma accum regs ----
    const float a0 = alpha[0];
    float2 b2[6];
    #pragma unroll
    for (int nt = 0; nt < 6; ++nt) {
        const int col = ncol + nt * 8 + (l & 3) * 2;
        b2[nt] = make_float2(bias[col], bias[col + 1]);
    }
    #pragma unroll
    for (int mt = 0; mt < 2; ++mt) {
        #pragma unroll
        for (int half = 0; half < 2; ++half) {
            const size_t pt = (size_t)(base + mrow + mt * 16 + (l >> 2) + half * 8);
            #pragma unroll
            for (int nt = 0; nt < 6; ++nt) {
                const int col = ncol + nt * 8 + (l & 3) * 2;
                float v0 = acc[mt][nt][2 * half]     + b2[nt].x;
                float v1 = acc[mt][nt][2 * half + 1] + b2[nt].y;
                if (resid != nullptr) {
                    const float2 r = *(const float2*)(resid + pt * CHN + col);
                    v0 += r.x; v1 += r.y;
                }
                v0 = (v0 > 0.f) ? v0 : a0 * v0;
                v1 = (v1 > 0.f) ? v1 : a0 * v1;
                if (out_half) {
                    *(__half2*)((__half*)outp + pt * CHN + col) = __floats2half2_rn(v0, v1);
                } else {
                    *(float2*)((float*)outp + pt * CHN + col) = make_float2(v0, v1);
                }
            }
        }
    }
}

extern "C" void kernel_launch(void* const* d_in, const int* in_sizes, int n_in,
                              void* d_out, int out_size)
{
    const float* feats = (const float*)d_in[0];
    const int*   idx   = (const int*)d_in[1];
    const int*   mask  = (const int*)d_in[2];
    const float* W1    = (const float*)d_in[3];
    const float* b1    = (const float*)d_in[4];
    const float* a1    = (const float*)d_in[5];
    const float* W2    = (const float*)d_in[6];
    const float* b2    = (const float*)d_in[7];
    const float* a2    = (const float*)d_in[8];

    __half *fh, *x1h, *wsp;
    cudaGetSymbolAddress((void**)&fh, g_fh);
    cudaGetSymbolAddress((void**)&x1h, g_x1h);
    cudaGetSymbolAddress((void**)&wsp, g_Wsp);

    static bool attr_done = false;
    if (!attr_done) {
        cudaFuncSetAttribute(sconv_hmma, cudaFuncAttributeMaxDynamicSharedMemorySize, SMEMTOT);
        attr_done = true;
    }

    const int nelem = NPTS * CHN;
    split_kernel<<<(nelem + 255) / 256, 256>>>(feats, fh, nelem);
    const int nw = 2 * NCHUNK * 2 * 32 * 104;
    wprep_kernel<<<(nw + 255) / 256, 256>>>(W1, W2);

    const size_t wstride = (size_t)NCHUNK * 6656;
    dim3 grid(NPTS / 128), block(NTHREADS);
    sconv_hmma<<<grid, block, SMEMTOT>>>(fh, nullptr, idx, mask,
                                         wsp, b1, a1, (void*)x1h, 1);
    sconv_hmma<<<grid, block, SMEMTOT>>>(x1h, feats, idx, mask,
                                         wsp + wstride, b2, a2, d_out, 0);
}

// round 9
// speedup vs baseline: 4.2535x; 1.0211x over previous
#include <cuda_runtime.h>
#include <cuda_fp16.h>
#include <cstdint>

#define NPTS 262144
#define CHN 96
#define KOFF 27
#define NCHUNK 81           // 27 offsets x 3 chunks of 32 K each
#define NTHREADS 256
#define NSTAGE 4

// SMEM layout (dynamic):
#define SIDX_OFF 0          // int[27][128] = 13824 B
#define A_OFF    13824      // 4 bufs x 10240 B (128 rows x 80B stride, fp16)
#define W_OFF    (13824 + 4 * 10240)        // 4 bufs x 13312 B (hi 6656 + lo 6656)
#define SMEMTOT  (W_OFF + 4 * 13312)        // 108032 B

// ---------------- static device buffers (no allocs allowed) ----------------
__device__ __align__(16) __half g_fh[(size_t)NPTS * CHN];    // feats fp16
__device__ __align__(16) __half g_x1h[(size_t)NPTS * CHN];   // layer-1 out fp16
// W split: [2 layers][81 chunks][2 (hi,lo)][32 k][104 n] fp16; chunk = 6656 halfs
__device__ __align__(16) __half g_Wsp[2 * NCHUNK * 2 * 32 * 104];

// ---------------- helpers ----------------
__device__ __forceinline__ uint32_t smem_u32(const void* p) {
    uint32_t a;
    asm("{ .reg .u64 t; cvta.to.shared.u64 t, %1; cvt.u32.u64 %0, t; }" : "=r"(a) : "l"(p));
    return a;
}
__device__ __forceinline__ void cpa16(uint32_t d, const void* s, int sz) {
    asm volatile("cp.async.cg.shared.global [%0], [%1], 16, %2;"
        :: "r"(d), "l"(__cvta_generic_to_global(s)), "r"(sz) : "memory");
}
__device__ __forceinline__ void ldm4(uint32_t* r, uint32_t addr) {
    asm volatile("ldmatrix.sync.aligned.m8n8.x4.shared.b16 {%0,%1,%2,%3}, [%4];"
        : "=r"(r[0]), "=r"(r[1]), "=r"(r[2]), "=r"(r[3]) : "r"(addr));
}
__device__ __forceinline__ void ldm4t(uint32_t* r, uint32_t addr) {
    asm volatile("ldmatrix.sync.aligned.m8n8.x4.trans.shared.b16 {%0,%1,%2,%3}, [%4];"
        : "=r"(r[0]), "=r"(r[1]), "=r"(r[2]), "=r"(r[3]) : "r"(addr));
}
__device__ __forceinline__ void mma16816(float* d, const uint32_t* a, uint32_t b0, uint32_t b1) {
    asm volatile("mma.sync.aligned.m16n8k16.row.col.f32.f16.f16.f32 "
        "{%0,%1,%2,%3},{%4,%5,%6,%7},{%8,%9},{%0,%1,%2,%3};"
        : "+f"(d[0]), "+f"(d[1]), "+f"(d[2]), "+f"(d[3])
        : "r"(a[0]), "r"(a[1]), "r"(a[2]), "r"(a[3]), "r"(b0), "r"(b1));
}

// ---------------- prep kernels ----------------
__global__ void split_kernel(const float* __restrict__ src, __half* __restrict__ dst, int n) {
    int i = blockIdx.x * blockDim.x + threadIdx.x;
    if (i < n) dst[i] = __float2half(src[i]);
}

__global__ void wprep_kernel(const float* __restrict__ W1, const float* __restrict__ W2) {
    int i = blockIdx.x * blockDim.x + threadIdx.x;   // over 2*81*2*32*104
    if (i >= 2 * NCHUNK * 2 * 32 * 104) return;
    int n = i % 104;
    int rest = i / 104;
    int kk = rest % 32;  rest /= 32;
    int part = rest % 2; rest /= 2;
    int c = rest % NCHUNK;
    int layer = rest / NCHUNK;
    float w = 0.f;
    if (n < CHN) {
        int k = c / 3, j = (c % 3) * 32 + kk;
        const float* W = layer ? W2 : W1;
        w = W[(size_t)k * CHN * CHN + (size_t)j * CHN + n];
    }
    __half hi = __float2half(w);
    __half lo = __float2half(w - __half2float(hi));
    g_Wsp[i] = part ? lo : hi;
}

// ---------------- main gather-GEMM layer kernel (fp16 2-term HMMA) ----------------
__global__ void __launch_bounds__(NTHREADS, 2)
sconv_hmma(const __half* __restrict__ fin,    // fp16 input [N, CH]
           const float* __restrict__ resid,   // fp32 residual or nullptr
           const int* __restrict__ nidx, const int* __restrict__ nmask,
           const __half* __restrict__ Wsp,    // layer slice: [81][2][32][104]
           const float* __restrict__ bias, const float* __restrict__ alpha,
           void* __restrict__ outp, int out_half)
{
    extern __shared__ unsigned char smem[];
    const uint32_t sbase = smem_u32(smem);
    const int tid = threadIdx.x;
    const int wid = tid >> 5, l = tid & 31;
    const int base = blockIdx.x * 128;
    int* sIdx = (int*)(smem + SIDX_OFF);

    // preload idx with mask folded in
    for (int o = tid; o < KOFF * 128; o += NTHREADS) {
        const int k = o >> 7, t = o & 127;
        const int row = nidx[(size_t)k * NPTS + base + t];
        sIdx[o] = nmask[(size_t)k * NPTS + base + t] ? row : -1;
    }
    __syncthreads();

    const int mrow = (wid & 3) * 32;     // warp M offset (32 pts)
    const int ncol = (wid >> 2) * 48;    // warp N offset (48 ch)
    const int grow = tid >> 1, gh = tid & 1;   // gather: 2 thr/point, 16 halfs each

    float acc[2][6][4];
    #pragma unroll
    for (int mt = 0; mt < 2; ++mt)
        #pragma unroll
        for (int nt = 0; nt < 6; ++nt)
            #pragma unroll
            for (int q = 0; q < 4; ++q) acc[mt][nt][q] = 0.f;

    // async prefetch of chunk c into stage buffer
    auto prefetch = [&](int c) {
        const int buf = c & (NSTAGE - 1);
        const int k = c / 3, cpart = c % 3;
        // A gather (128 pts x 32 halfs, zero-fill masked rows)
        const int gidx = sIdx[(k << 7) + grow];
        const __half* gsrc = fin + (size_t)(gidx < 0 ? 0 : gidx) * CHN + cpart * 32 + gh * 16;
        const int sz = (gidx < 0) ? 0 : 16;
        const uint32_t sa = sbase + A_OFF + buf * 10240 + grow * 80 + gh * 32;
        cpa16(sa, gsrc, sz);
        cpa16(sa + 16, gsrc + 8, sz);
        // W copy: 13312 B contiguous = 832 uint4
        const uint4* ws = (const uint4*)(Wsp + (size_t)c * 6656);
        const uint32_t wd = sbase + W_OFF + buf * 13312;
        cpa16(wd + tid * 16,         ws + tid,       16);
        cpa16(wd + (tid + 256) * 16, ws + tid + 256, 16);
        cpa16(wd + (tid + 512) * 16, ws + tid + 512, 16);
        if (tid < 64) cpa16(wd + (tid + 768) * 16, ws + tid + 768, 16);
        asm volatile("cp.async.commit_group;" ::: "memory");
    };

    prefetch(0);
    prefetch(1);
    prefetch(2);

    // ldmatrix lane addressing
    const int arow_off = (l & 7) + ((l >> 3) & 1) * 8;
    const int acol_off = ((l >> 4) & 1) * 8;

    for (int c = 0; c < NCHUNK; ++c) {
        const int buf = c & (NSTAGE - 1);
        // chunk c complete when at most 2 newer groups are pending
        asm volatile("cp.async.wait_group 2;" ::: "memory");
        __syncthreads();   // data visible + all warps done with MMA(c-1) -> buf (c+3)&3 free
        if (c + 3 < NCHUNK) prefetch(c + 3);

        const uint32_t aB  = sbase + A_OFF + buf * 10240;
        const uint32_t wBH = sbase + W_OFF + buf * 13312;
        const uint32_t wBL = wBH + 6656;

        #pragma unroll
        for (int kh = 0; kh < 2; ++kh) {
            uint32_t a[2][4];
            #pragma unroll
            for (int mt = 0; mt < 2; ++mt) {
                const int r = mrow + mt * 16 + arow_off;
                ldm4(a[mt], aB + (uint32_t)(r * 80 + (kh * 16 + acol_off) * 2));
            }
            const int kr = kh * 16 + arow_off;
            #pragma unroll
            for (int np = 0; np < 3; ++np) {
                const int nc = ncol + np * 16 + acol_off;
                const uint32_t woff = (uint32_t)(kr * 208 + nc * 2);
                uint32_t bh[4], bl[4];
                ldm4t(bh, wBH + woff);
                ldm4t(bl, wBL + woff);
                #pragma unroll
                for (int hf = 0; hf < 2; ++hf) {
                    const int nt = np * 2 + hf;
                    #pragma unroll
                    for (int mt = 0; mt < 2; ++mt) {
                        mma16816(acc[mt][nt], a[mt], bh[2 * hf], bh[2 * hf + 1]); // A*Whi
                        mma16816(acc[mt][nt], a[mt], bl[2 * hf], bl[2 * hf + 1]); // A*Wlo
                    }
                }
            }
        }
    }

    // ---- epilogue: bias, optional residual, PReLU, store from mma accum regs ----
    const float a0 = alpha[0];
    float2 b2[6];
    #pragma unroll
    for (int nt = 0; nt < 6; ++nt) {
        const int col = ncol + nt * 8 + (l & 3) * 2;
        b2[nt] = make_float2(bias[col], bias[col + 1]);
    }
    #pragma unroll
    for (int mt = 0; mt < 2; ++mt) {
        #pragma unroll
        for (int half = 0; half < 2; ++half) {
            const size_t pt = (size_t)(base + mrow + mt * 16 + (l >> 2) + half * 8);
            #pragma unroll
            for (int nt = 0; nt < 6; ++nt) {
                const int col = ncol + nt * 8 + (l & 3) * 2;
                float v0 = acc[mt][nt][2 * half]     + b2[nt].x;
                float v1 = acc[mt][nt][2 * half + 1] + b2[nt].y;
                if (resid != nullptr) {
                    const float2 r = *(const float2*)(resid + pt * CHN + col);
                    v0 += r.x; v1 += r.y;
                }
                v0 = (v0 > 0.f) ? v0 : a0 * v0;
                v1 = (v1 > 0.f) ? v1 : a0 * v1;
                if (out_half) {
                    *(__half2*)((__half*)outp + pt * CHN + col) = __floats2half2_rn(v0, v1);
                } else {
                    *(float2*)((float*)outp + pt * CHN + col) = make_float2(v0, v1);
                }
            }
        }
    }
}

extern "C" void kernel_launch(void* const* d_in, const int* in_sizes, int n_in,
                              void* d_out, int out_size)
{
    const float* feats = (const float*)d_in[0];
    const int*   idx   = (const int*)d_in[1];
    const int*   mask  = (const int*)d_in[2];
    const float* W1    = (const float*)d_in[3];
    const float* b1    = (const float*)d_in[4];
    const float* a1    = (const float*)d_in[5];
    const float* W2    = (const float*)d_in[6];
    const float* b2    = (const float*)d_in[7];
    const float* a2    = (const float*)d_in[8];

    __half *fh, *x1h, *wsp;
    cudaGetSymbolAddress((void**)&fh, g_fh);
    cudaGetSymbolAddress((void**)&x1h, g_x1h);
    cudaGetSymbolAddress((void**)&wsp, g_Wsp);

    static bool attr_done = false;
    if (!attr_done) {
        cudaFuncSetAttribute(sconv_hmma, cudaFuncAttributeMaxDynamicSharedMemorySize, SMEMTOT);
        attr_done = true;
    }

    const int nelem = NPTS * CHN;
    split_kernel<<<(nelem + 255) / 256, 256>>>(feats, fh, nelem);
    const int nw = 2 * NCHUNK * 2 * 32 * 104;
    wprep_kernel<<<(nw + 255) / 256, 256>>>(W1, W2);

    const size_t wstride = (size_t)NCHUNK * 6656;
    dim3 grid(NPTS / 128), block(NTHREADS);
    sconv_hmma<<<grid, block, SMEMTOT>>>(fh, nullptr, idx, mask,
                                         wsp, b1, a1, (void*)x1h, 1);
    sconv_hmma<<<grid, block, SMEMTOT>>>(x1h, feats, idx, mask,
                                         wsp + wstride, b2, a2, d_out, 0);
}

// round 10
// speedup vs baseline: 6.7533x; 1.5877x over previous
#include <cuda_runtime.h>
#include <cuda_fp16.h>
#include <cstdint>

#define NPTS 262144
#define CHN 96
#define KOFF 27
#define NCHUNK 81           // 27 offsets x 3 chunks of 32 K each
#define NTHREADS 256
#define NSTAGE 4

// SMEM layout (dynamic):
#define SIDX_OFF 0          // int[27][128] = 13824 B
#define A_OFF    13824      // 4 bufs x 10240 B (128 rows x 80B stride, fp16)
#define W_OFF    (13824 + 4 * 10240)        // 4 bufs x 6656 B
#define SMEMTOT  (W_OFF + 4 * 6656)         // 81408 B

// ---------------- static device buffers (no allocs allowed) ----------------
__device__ __align__(16) __half g_fh[(size_t)NPTS * CHN];    // feats fp16
__device__ __align__(16) __half g_x1h[(size_t)NPTS * CHN];   // layer-1 out fp16
// W fp16, padded: [2 layers][81 chunks][32 k][104 n]; chunk = 3328 halfs
__device__ __align__(16) __half g_Wh[2 * NCHUNK * 32 * 104];

// ---------------- helpers ----------------
__device__ __forceinline__ uint32_t smem_u32(const void* p) {
    uint32_t a;
    asm("{ .reg .u64 t; cvta.to.shared.u64 t, %1; cvt.u32.u64 %0, t; }" : "=r"(a) : "l"(p));
    return a;
}
__device__ __forceinline__ void cpa16(uint32_t d, const void* s, int sz) {
    asm volatile("cp.async.cg.shared.global [%0], [%1], 16, %2;"
        :: "r"(d), "l"(__cvta_generic_to_global(s)), "r"(sz) : "memory");
}
__device__ __forceinline__ void ldm4(uint32_t* r, uint32_t addr) {
    asm volatile("ldmatrix.sync.aligned.m8n8.x4.shared.b16 {%0,%1,%2,%3}, [%4];"
        : "=r"(r[0]), "=r"(r[1]), "=r"(r[2]), "=r"(r[3]) : "r"(addr));
}
__device__ __forceinline__ void ldm4t(uint32_t* r, uint32_t addr) {
    asm volatile("ldmatrix.sync.aligned.m8n8.x4.trans.shared.b16 {%0,%1,%2,%3}, [%4];"
        : "=r"(r[0]), "=r"(r[1]), "=r"(r[2]), "=r"(r[3]) : "r"(addr));
}
__device__ __forceinline__ void mma16816(float* d, const uint32_t* a, uint32_t b0, uint32_t b1) {
    asm volatile("mma.sync.aligned.m16n8k16.row.col.f32.f16.f16.f32 "
        "{%0,%1,%2,%3},{%4,%5,%6,%7},{%8,%9},{%0,%1,%2,%3};"
        : "+f"(d[0]), "+f"(d[1]), "+f"(d[2]), "+f"(d[3])
        : "r"(a[0]), "r"(a[1]), "r"(a[2]), "r"(a[3]), "r"(b0), "r"(b1));
}

// ---------------- prep kernels ----------------
__global__ void split_kernel(const float* __restrict__ src, __half* __restrict__ dst, int n) {
    int i = blockIdx.x * blockDim.x + threadIdx.x;
    if (i < n) dst[i] = __float2half(src[i]);
}

__global__ void wprep_kernel(const float* __restrict__ W1, const float* __restrict__ W2) {
    int i = blockIdx.x * blockDim.x + threadIdx.x;   // over 2*81*32*104
    if (i >= 2 * NCHUNK * 32 * 104) return;
    int n = i % 104;
    int rest = i / 104;
    int kk = rest % 32;  rest /= 32;
    int c = rest % NCHUNK;
    int layer = rest / NCHUNK;
    float w = 0.f;
    if (n < CHN) {
        int k = c / 3, j = (c % 3) * 32 + kk;
        const float* W = layer ? W2 : W1;
        w = W[(size_t)k * CHN * CHN + (size_t)j * CHN + n];
    }
    g_Wh[i] = __float2half(w);
}

// ---------------- main gather-GEMM layer kernel (fp16 HMMA) ----------------
__global__ void __launch_bounds__(NTHREADS, 2)
sconv_hmma(const __half* __restrict__ fin,    // fp16 input [N, CH]
           const float* __restrict__ resid,   // fp32 residual or nullptr
           const int* __restrict__ nidx, const int* __restrict__ nmask,
           const __half* __restrict__ Wh,     // layer slice: [81][32][104]
           const float* __restrict__ bias, const float* __restrict__ alpha,
           void* __restrict__ outp, int out_half)
{
    extern __shared__ unsigned char smem[];
    const uint32_t sbase = smem_u32(smem);
    const int tid = threadIdx.x;
    const int wid = tid >> 5, l = tid & 31;
    const int base = blockIdx.x * 128;
    int* sIdx = (int*)(smem + SIDX_OFF);

    // preload idx with mask folded in
    for (int o = tid; o < KOFF * 128; o += NTHREADS) {
        const int k = o >> 7, t = o & 127;
        const int row = nidx[(size_t)k * NPTS + base + t];
        sIdx[o] = nmask[(size_t)k * NPTS + base + t] ? row : -1;
    }
    __syncthreads();

    const int mrow = (wid & 3) * 32;     // warp M offset (32 pts)
    const int ncol = (wid >> 2) * 48;    // warp N offset (48 ch)
    const int grow = tid >> 1, gh = tid & 1;   // gather: 2 thr/point, 16 halfs each

    float acc[2][6][4];
    #pragma unroll
    for (int mt = 0; mt < 2; ++mt)
        #pragma unroll
        for (int nt = 0; nt < 6; ++nt)
            #pragma unroll
            for (int q = 0; q < 4; ++q) acc[mt][nt][q] = 0.f;

    // async prefetch of chunk c into stage buffer
    auto prefetch = [&](int c) {
        const int buf = c & (NSTAGE - 1);
        const int k = c / 3, cpart = c % 3;
        // A gather (128 pts x 32 halfs, zero-fill masked rows)
        const int gidx = sIdx[(k << 7) + grow];
        const __half* gsrc = fin + (size_t)(gidx < 0 ? 0 : gidx) * CHN + cpart * 32 + gh * 16;
        const int sz = (gidx < 0) ? 0 : 16;
        const uint32_t sa = sbase + A_OFF + buf * 10240 + grow * 80 + gh * 32;
        cpa16(sa, gsrc, sz);
        cpa16(sa + 16, gsrc + 8, sz);
        // W copy: 6656 B contiguous = 416 uint4
        const uint4* ws = (const uint4*)(Wh + (size_t)c * 3328);
        const uint32_t wd = sbase + W_OFF + buf * 6656;
        cpa16(wd + tid * 16, ws + tid, 16);
        if (tid < 160) cpa16(wd + (tid + 256) * 16, ws + tid + 256, 16);
        asm volatile("cp.async.commit_group;" ::: "memory");
    };

    prefetch(0);
    prefetch(1);
    prefetch(2);

    // ldmatrix lane addressing
    const int arow_off = (l & 7) + ((l >> 3) & 1) * 8;
    const int acol_off = ((l >> 4) & 1) * 8;

    for (int c = 0; c < NCHUNK; ++c) {
        const int buf = c & (NSTAGE - 1);
        // chunk c complete when at most 2 newer groups are pending
        asm volatile("cp.async.wait_group 2;" ::: "memory");
        __syncthreads();   // data visible + all warps done with MMA(c-1) -> buf (c+3)&3 free
        if (c + 3 < NCHUNK) prefetch(c + 3);

        const uint32_t aB = sbase + A_OFF + buf * 10240;
        const uint32_t wB = sbase + W_OFF + buf * 6656;

        #pragma unroll
        for (int kh = 0; kh < 2; ++kh) {
            uint32_t a[2][4];
            #pragma unroll
            for (int mt = 0; mt < 2; ++mt) {
                const int r = mrow + mt * 16 + arow_off;
                ldm4(a[mt], aB + (uint32_t)(r * 80 + (kh * 16 + acol_off) * 2));
            }
            const int kr = kh * 16 + arow_off;
            #pragma unroll
            for (int np = 0; np < 3; ++np) {
                const int nc = ncol + np * 16 + acol_off;
                uint32_t b[4];
                ldm4t(b, wB + (uint32_t)(kr * 208 + nc * 2));
                #pragma unroll
                for (int hf = 0; hf < 2; ++hf) {
                    const int nt = np * 2 + hf;
                    #pragma unroll
                    for (int mt = 0; mt < 2; ++mt)
                        mma16816(acc[mt][nt], a[mt], b[2 * hf], b[2 * hf + 1]);
                }
            }
        }
    }

    // ---- epilogue: bias, optional residual, PReLU, store from mma accum regs ----
    const float a0 = alpha[0];
    float2 b2[6];
    #pragma unroll
    for (int nt = 0; nt < 6; ++nt) {
        const int col = ncol + nt * 8 + (l & 3) * 2;
        b2[nt] = make_float2(bias[col], bias[col + 1]);
    }
    #pragma unroll
    for (int mt = 0; mt < 2; ++mt) {
        #pragma unroll
        for (int half = 0; half < 2; ++half) {
            const size_t pt = (size_t)(base + mrow + mt * 16 + (l >> 2) + half * 8);
            #pragma unroll
            for (int nt = 0; nt < 6; ++nt) {
                const int col = ncol + nt * 8 + (l & 3) * 2;
                float v0 = acc[mt][nt][2 * half]     + b2[nt].x;
                float v1 = acc[mt][nt][2 * half + 1] + b2[nt].y;
                if (resid != nullptr) {
                    const float2 r = *(const float2*)(resid + pt * CHN + col);
                    v0 += r.x; v1 += r.y;
                }
                v0 = (v0 > 0.f) ? v0 : a0 * v0;
                v1 = (v1 > 0.f) ? v1 : a0 * v1;
                if (out_half) {
                    *(__half2*)((__half*)outp + pt * CHN + col) = __floats2half2_rn(v0, v1);
                } else {
                    *(float2*)((float*)outp + pt * CHN + col) = make_float2(v0, v1);
                }
            }
        }
    }
}

extern "C" void kernel_launch(void* const* d_in, const int* in_sizes, int n_in,
                              void* d_out, int out_size)
{
    const float* feats = (const float*)d_in[0];
    const int*   idx   = (const int*)d_in[1];
    const int*   mask  = (const int*)d_in[2];
    const float* W1    = (const float*)d_in[3];
    const float* b1    = (const float*)d_in[4];
    const float* a1    = (const float*)d_in[5];
    const float* W2    = (const float*)d_in[6];
    const float* b2    = (const float*)d_in[7];
    const float* a2    = (const float*)d_in[8];

    __half *fh, *x1h, *wh;
    cudaGetSymbolAddress((void**)&fh, g_fh);
    cudaGetSymbolAddress((void**)&x1h, g_x1h);
    cudaGetSymbolAddress((void**)&wh, g_Wh);

    static bool attr_done = false;
    if (!attr_done) {
        cudaFuncSetAttribute(sconv_hmma, cudaFuncAttributeMaxDynamicSharedMemorySize, SMEMTOT);
        attr_done = true;
    }

    const int nelem = NPTS * CHN;
    split_kernel<<<(nelem + 255) / 256, 256>>>(feats, fh, nelem);
    const int nw = 2 * NCHUNK * 32 * 104;
    wprep_kernel<<<(nw + 255) / 256, 256>>>(W1, W2);

    const size_t wstride = (size_t)NCHUNK * 3328;
    dim3 grid(NPTS / 128), block(NTHREADS);
    sconv_hmma<<<grid, block, SMEMTOT>>>(fh, nullptr, idx, mask,
                                         wh, b1, a1, (void*)x1h, 1);
    sconv_hmma<<<grid, block, SMEMTOT>>>(x1h, feats, idx, mask,
                                         wh + wstride, b2, a2, d_out, 0);
}